// round 8
// baseline (speedup 1.0000x reference)
#include <cuda_runtime.h>
#include <math.h>
#include <float.h>
#include <stdint.h>

#define BB 16
#define DD 512
#define TT 2048
#define NQ 9
#define CS 1024
#define CD 8
#define TTILE 16
#define NTHREADS 256
#define WPITCH 516   // win row pitch (floats): c-rows start bank 4c -> c-pair conflict-free

// ---------------- precomputed (normalized) parameter scratch ----------------
__device__ float g_win[NQ * CD * DD];   // weight-normed in_proj  (q, c, d)
__device__ float g_wout[NQ * DD * CD];  // weight-normed out_proj (q, d, c)
__device__ float g_cbn[NQ * CS * CD];   // l2-normalized codebook
__device__ float g_csq[NQ * CS];        // sum(c_norm^2) per code

__global__ void rvq_precompute(const float* __restrict__ iv, const float* __restrict__ ig,
                               const float* __restrict__ ov, const float* __restrict__ og,
                               const float* __restrict__ cb) {
    int q = blockIdx.x;
    int tid = threadIdx.x;           // 256 threads
    int wid = tid >> 5, lane = tid & 31;

    if (wid < CD) {
        int c = wid;
        const float* v = iv + ((size_t)q * CD + c) * DD;
        float ss = 0.f;
        for (int d = lane; d < DD; d += 32) { float x = v[d]; ss = fmaf(x, x, ss); }
        #pragma unroll
        for (int o = 16; o > 0; o >>= 1) ss += __shfl_xor_sync(0xffffffffu, ss, o);
        float nrm = __fsqrt_rn(ss);
        float g = ig[q * CD + c];
        for (int d = lane; d < DD; d += 32)
            g_win[((size_t)q * CD + c) * DD + d] = __fdiv_rn(g * v[d], nrm);
    }
    for (int r = tid; r < DD; r += 256) {
        const float* v = ov + ((size_t)q * DD + r) * CD;
        float ss = 0.f;
        #pragma unroll
        for (int c = 0; c < CD; c++) { float x = v[c]; ss = fmaf(x, x, ss); }
        float nrm = __fsqrt_rn(ss);
        float g = og[q * DD + r];
        #pragma unroll
        for (int c = 0; c < CD; c++)
            g_wout[((size_t)q * DD + r) * CD + c] = __fdiv_rn(g * v[c], nrm);
    }
    for (int s = tid; s < CS; s += 256) {
        const float* v = cb + ((size_t)q * CS + s) * CD;
        float ss = 0.f;
        #pragma unroll
        for (int c = 0; c < CD; c++) { float x = v[c]; ss = fmaf(x, x, ss); }
        float den = fmaxf(__fsqrt_rn(ss), 1e-12f);
        float cs2 = 0.f;
        #pragma unroll
        for (int c = 0; c < CD; c++) {
            float cn = __fdiv_rn(v[c], den);
            g_cbn[((size_t)q * CS + s) * CD + c] = cn;
            cs2 = fmaf(cn, cn, cs2);
        }
        g_csq[q * CS + s] = cs2;
    }
}

// ---------------- main fused RVQ kernel (2 independent CTAs/SM) ----------------
struct SMem {
    float4 cbn4[CS * 2];          // 32768
    float4 csq4[CS / 4];          // 4096
    float  win[CD * WPITCH];      // 16512 (pitch 516)
    float  wout[DD * CD];         // 16384
    float  ob[DD];                // 2048
    float  res[DD * TTILE];       // 32768
    float  part[2][CD][TTILE];    // 1024  z_i d-half partials
    float  zqs[CD][TTILE];        // 512
    float  redb[16][TTILE];       // 1024
    int    redi[16][TTILE];       // 1024
    float  ib[CD];                // 32
};  // 108192 B -> 2 CTAs/SM

__device__ __forceinline__ float dist8(float4 ca, float4 cb2,
                                       float e0, float e1, float e2, float e3,
                                       float e4, float e5, float e6, float e7,
                                       float eq, float cs) {
    float dot = e0 * ca.x;
    dot = fmaf(e1, ca.y, dot); dot = fmaf(e2, ca.z, dot); dot = fmaf(e3, ca.w, dot);
    dot = fmaf(e4, cb2.x, dot); dot = fmaf(e5, cb2.y, dot);
    dot = fmaf(e6, cb2.z, dot); dot = fmaf(e7, cb2.w, dot);
    return fmaf(-2.0f, dot, eq) + cs;   // matches reference ((enc_sq - 2*dot) + csq)
}

__global__ void __launch_bounds__(NTHREADS, 2)
rvq_kernel(const float* __restrict__ z,
           const float* __restrict__ ib_g,
           const float* __restrict__ ob_g,
           const float* __restrict__ cbraw,
           float* __restrict__ out) {
    extern __shared__ unsigned char smraw[];
    SMem& sm = *reinterpret_cast<SMem*>(smraw);

    const int tid = threadIdx.x;
    const int b = blockIdx.y;
    const int t0 = blockIdx.x * TTILE;

    float* out_codes = out;
    float* out_zO  = out + (size_t)BB * NQ * TT;
    float* out_zis = out_zO + (size_t)BB * DD * TT;
    float* out_zqs = out_zis + (size_t)BB * NQ * CD * TT;
    float* out_zos = out_zqs + (size_t)BB * NQ * CD * TT;

    // ---- load residual tile: res[d][tl], pitch 16 ----
    const float* zb = z + (size_t)b * DD * TT + t0;
    {
        float4* res4 = reinterpret_cast<float4*>(&sm.res[0]);
        for (int k = 0; k < 8; k++) {
            int f = tid + 256 * k;          // 2048 float4 total
            int d = f >> 2, j = f & 3;
            res4[f] = reinterpret_cast<const float4*>(zb + (size_t)d * TT)[j];
        }
    }

    const int wid  = tid >> 5;
    const int lane = tid & 31;
    const int gg   = lane >> 4;         // 0/1 subgroup
    const int tl   = lane & 15;         // local t column

    // z_i roles: h = d-half, cpair; lane: c2 = gg
    const int zi_h = wid >> 2;
    const int zi_c = (wid & 3) * 2 + gg;
    // NN role: chunk of 64 codes
    const int chunk = wid * 2 + gg;

    for (int q = 0; q < NQ; q++) {
        __syncthreads();   // res settled; previous-q tables free
        // ---- stage per-quantizer tables ----
        {
            const float4* s1 = reinterpret_cast<const float4*>(g_win + (size_t)q * CD * DD);
            for (int i = tid; i < CD * DD / 4; i += NTHREADS) {
                int c = i >> 7, j = i & 127;
                *reinterpret_cast<float4*>(&sm.win[c * WPITCH + 4 * j]) = s1[i];
            }
            const float4* s2 = reinterpret_cast<const float4*>(g_wout + (size_t)q * DD * CD);
            float4* d2 = reinterpret_cast<float4*>(&sm.wout[0]);
            for (int i = tid; i < DD * CD / 4; i += NTHREADS) d2[i] = s2[i];
            const float4* s3 = reinterpret_cast<const float4*>(g_cbn + (size_t)q * CS * CD);
            for (int i = tid; i < CS * 2; i += NTHREADS) sm.cbn4[i] = s3[i];
            const float4* s4 = reinterpret_cast<const float4*>(g_csq + (size_t)q * CS);
            for (int i = tid; i < CS / 4; i += NTHREADS) sm.csq4[i] = s4[i];
            const float4* s5 = reinterpret_cast<const float4*>(ob_g + (size_t)q * DD);
            float4* d5 = reinterpret_cast<float4*>(&sm.ob[0]);
            for (int i = tid; i < DD / 4; i += NTHREADS) d5[i] = s5[i];
            if (tid < CD) sm.ib[tid] = ib_g[q * CD + tid];
        }
        __syncthreads();

        // ---- z_i partials: warp = (d-half, c-pair); lane = (c2, tl) ----
        {
            const float4* wr4 = reinterpret_cast<const float4*>(
                &sm.win[zi_c * WPITCH + zi_h * 256]);
            const float* rr = &sm.res[(size_t)(zi_h * 256) * TTILE + tl];
            float a0 = 0.f, a1 = 0.f, a2 = 0.f, a3 = 0.f;
            #pragma unroll 4
            for (int i = 0; i < 64; i++) {
                float4 w = wr4[i];                      // 2-addr broadcast LDS.128
                int dof = 4 * i * TTILE;
                a0 = fmaf(w.x, rr[dof             ], a0);
                a1 = fmaf(w.y, rr[dof + TTILE     ], a1);
                a2 = fmaf(w.z, rr[dof + 2 * TTILE ], a2);
                a3 = fmaf(w.w, rr[dof + 3 * TTILE ], a3);
            }
            sm.part[zi_h][zi_c][tl] = (a0 + a1) + (a2 + a3);
        }
        __syncthreads();

        // ---- NN: thread = (chunk, tl); redundant norm from partials ----
        {
            float zc[CD];
            #pragma unroll
            for (int c = 0; c < CD; c++)
                zc[c] = (sm.part[0][c][tl] + sm.part[1][c][tl]) + sm.ib[c];
            float ss = zc[0] * zc[0];
            #pragma unroll
            for (int c = 1; c < CD; c++) ss = fmaf(zc[c], zc[c], ss);
            float den = fmaxf(__fsqrt_rn(ss), 1e-12f);
            float e0 = __fdiv_rn(zc[0], den), e1 = __fdiv_rn(zc[1], den);
            float e2 = __fdiv_rn(zc[2], den), e3 = __fdiv_rn(zc[3], den);
            float e4 = __fdiv_rn(zc[4], den), e5 = __fdiv_rn(zc[5], den);
            float e6 = __fdiv_rn(zc[6], den), e7 = __fdiv_rn(zc[7], den);
            float eq = e0 * e0;
            eq = fmaf(e1, e1, eq); eq = fmaf(e2, e2, eq); eq = fmaf(e3, e3, eq);
            eq = fmaf(e4, e4, eq); eq = fmaf(e5, e5, eq); eq = fmaf(e6, e6, eq);
            eq = fmaf(e7, e7, eq);

            const int s0 = chunk * 64;
            float b0 = FLT_MAX, b1 = FLT_MAX, b2 = FLT_MAX, b3 = FLT_MAX;
            int   i0 = 0, i1 = 0, i2 = 0, i3 = 0;
            #pragma unroll 2
            for (int s = s0; s < s0 + 64; s += 4) {
                float4 cs4 = sm.csq4[s >> 2];
                float dA = dist8(sm.cbn4[2 * s + 0], sm.cbn4[2 * s + 1], e0,e1,e2,e3,e4,e5,e6,e7, eq, cs4.x);
                float dB = dist8(sm.cbn4[2 * s + 2], sm.cbn4[2 * s + 3], e0,e1,e2,e3,e4,e5,e6,e7, eq, cs4.y);
                float dC = dist8(sm.cbn4[2 * s + 4], sm.cbn4[2 * s + 5], e0,e1,e2,e3,e4,e5,e6,e7, eq, cs4.z);
                float dDv= dist8(sm.cbn4[2 * s + 6], sm.cbn4[2 * s + 7], e0,e1,e2,e3,e4,e5,e6,e7, eq, cs4.w);
                if (dA < b0) { b0 = dA; i0 = s; }
                if (dB < b1) { b1 = dB; i1 = s + 1; }
                if (dC < b2) { b2 = dC; i2 = s + 2; }
                if (dDv< b3) { b3 = dDv; i3 = s + 3; }
            }
            if (b1 < b0 || (b1 == b0 && i1 < i0)) { b0 = b1; i0 = i1; }
            if (b2 < b0 || (b2 == b0 && i2 < i0)) { b0 = b2; i0 = i2; }
            if (b3 < b0 || (b3 == b0 && i3 < i0)) { b0 = b3; i0 = i3; }
            sm.redb[chunk][tl] = b0;
            sm.redi[chunk][tl] = i0;
        }
        __syncthreads();

        // ---- z_q: thread = (c = wid, gg, tl); redundant argmin merge ----
        {
            const int c = wid;
            float bb = sm.redb[0][tl]; int bi = sm.redi[0][tl];
            #pragma unroll
            for (int g = 1; g < 16; g++) {
                float v = sm.redb[g][tl];
                if (v < bb) { bb = v; bi = sm.redi[g][tl]; }   // chunks ascending
            }
            float ziv = (sm.part[0][c][tl] + sm.part[1][c][tl]) + sm.ib[c];
            float raw = __ldg(&cbraw[((size_t)q * CS + bi) * CD + c]);
            float zqv = ziv + (raw - ziv);
            if (gg == 0) {
                if (c == 0)
                    out_codes[((size_t)b * NQ + q) * TT + t0 + tl] = (float)bi;
                sm.zqs[c][tl] = zqv;
                out_zis[(((size_t)b * NQ + q) * CD + c) * TT + t0 + tl] = ziv;
                out_zqs[(((size_t)b * NQ + q) * CD + c) * TT + t0 + tl] = zqv;
            }
        }
        __syncthreads();

        // ---- z_o: thread = (wid, gg, tl); d = wid*64 + 2i + gg (parity split) ----
        {
            const float q0 = sm.zqs[0][tl], q1 = sm.zqs[1][tl], q2 = sm.zqs[2][tl], q3 = sm.zqs[3][tl];
            const float q4 = sm.zqs[4][tl], q5 = sm.zqs[5][tl], q6 = sm.zqs[6][tl], q7 = sm.zqs[7][tl];
            const float4* wo4 = reinterpret_cast<const float4*>(&sm.wout[0]);
            float* zosb = out_zos + (((size_t)b * NQ + q) * DD) * TT + t0 + tl;
            const int dbase = wid * 64 + gg;
            #pragma unroll 4
            for (int i = 0; i < 32; i++) {
                int d = dbase + 2 * i;
                float4 wa = wo4[2 * d], wb = wo4[2 * d + 1];
                float dot = q0 * wa.x;
                dot = fmaf(q1, wa.y, dot); dot = fmaf(q2, wa.z, dot); dot = fmaf(q3, wa.w, dot);
                dot = fmaf(q4, wb.x, dot); dot = fmaf(q5, wb.y, dot);
                dot = fmaf(q6, wb.z, dot); dot = fmaf(q7, wb.w, dot);
                float zo = dot + sm.ob[d];
                zosb[(size_t)d * TT] = zo;
                sm.res[d * TTILE + tl] -= zo;
            }
        }
    }

    __syncthreads();
    // ---- z_O = z - residual_final ----
    {
        const float* zsrc = zb + tl;
        float* zOb = out_zO + (size_t)b * DD * TT + t0 + tl;
        const int dbase = wid * 64 + gg;
        #pragma unroll 4
        for (int i = 0; i < 32; i++) {
            int d = dbase + 2 * i;
            zOb[(size_t)d * TT] = zsrc[(size_t)d * TT] - sm.res[d * TTILE + tl];
        }
    }
}

extern "C" void kernel_launch(void* const* d_in, const int* in_sizes, int n_in,
                              void* d_out, int out_size) {
    const float* z    = (const float*)d_in[0];
    const float* in_v = (const float*)d_in[1];
    const float* in_g = (const float*)d_in[2];
    const float* in_b = (const float*)d_in[3];
    const float* out_v= (const float*)d_in[4];
    const float* out_g= (const float*)d_in[5];
    const float* out_b= (const float*)d_in[6];
    const float* cb   = (const float*)d_in[7];
    float* out = (float*)d_out;

    rvq_precompute<<<NQ, 256>>>(in_v, in_g, out_v, out_g, cb);

    cudaFuncSetAttribute(rvq_kernel, cudaFuncAttributeMaxDynamicSharedMemorySize,
                         (int)sizeof(SMem));
    dim3 grid(TT / TTILE, BB);
    rvq_kernel<<<grid, NTHREADS, sizeof(SMem)>>>(z, in_b, out_b, cb, out);
}

// round 10
// speedup vs baseline: 1.1506x; 1.1506x over previous
#include <cuda_runtime.h>
#include <math.h>
#include <float.h>
#include <stdint.h>

#define BB 16
#define DD 512
#define TT 2048
#define NQ 9
#define CS 1024
#define CD 8
#define TTILE 64
#define NTHREADS 512

// ---------------- precomputed (normalized) parameter scratch ----------------
__device__ float g_win[NQ * CD * DD];    // weight-normed in_proj, c-major (q, c, d)  [q=0 standalone]
__device__ float g_winT[NQ * DD * CD];   // weight-normed in_proj, d-major (q, d, c)  [fused path]
__device__ float g_wout[NQ * DD * CD];   // weight-normed out_proj (q, d, c)
__device__ float g_cbn[NQ * CS * CD];    // l2-normalized codebook
__device__ float g_csq[NQ * CS];         // sum(c_norm^2) per code

__global__ void rvq_precompute(const float* __restrict__ iv, const float* __restrict__ ig,
                               const float* __restrict__ ov, const float* __restrict__ og,
                               const float* __restrict__ cb) {
    int q = blockIdx.x;
    int tid = threadIdx.x;           // 256 threads
    int wid = tid >> 5, lane = tid & 31;

    if (wid < CD) {
        int c = wid;
        const float* v = iv + ((size_t)q * CD + c) * DD;
        float ss = 0.f;
        for (int d = lane; d < DD; d += 32) { float x = v[d]; ss = fmaf(x, x, ss); }
        #pragma unroll
        for (int o = 16; o > 0; o >>= 1) ss += __shfl_xor_sync(0xffffffffu, ss, o);
        float nrm = __fsqrt_rn(ss);
        float g = ig[q * CD + c];
        for (int d = lane; d < DD; d += 32) {
            float w = __fdiv_rn(g * v[d], nrm);
            g_win[((size_t)q * CD + c) * DD + d] = w;
            g_winT[((size_t)q * DD + d) * CD + c] = w;
        }
    }
    for (int r = tid; r < DD; r += 256) {
        const float* v = ov + ((size_t)q * DD + r) * CD;
        float ss = 0.f;
        #pragma unroll
        for (int c = 0; c < CD; c++) { float x = v[c]; ss = fmaf(x, x, ss); }
        float nrm = __fsqrt_rn(ss);
        float g = og[q * DD + r];
        #pragma unroll
        for (int c = 0; c < CD; c++)
            g_wout[((size_t)q * DD + r) * CD + c] = __fdiv_rn(g * v[c], nrm);
    }
    for (int s = tid; s < CS; s += 256) {
        const float* v = cb + ((size_t)q * CS + s) * CD;
        float ss = 0.f;
        #pragma unroll
        for (int c = 0; c < CD; c++) { float x = v[c]; ss = fmaf(x, x, ss); }
        float den = fmaxf(__fsqrt_rn(ss), 1e-12f);
        float cs2 = 0.f;
        #pragma unroll
        for (int c = 0; c < CD; c++) {
            float cn = __fdiv_rn(v[c], den);
            g_cbn[((size_t)q * CS + s) * CD + c] = cn;
            cs2 = fmaf(cn, cn, cs2);
        }
        g_csq[q * CS + s] = cs2;
    }
}

// ---------------- main fused RVQ kernel ----------------
struct SMem {
    float4 cbn4[CS * 2];          // 32768  normalized codebook
    float  res[DD][TTILE];        // 131072 residual tile
    float4 winTn[DD * 2];         // 16384  in_proj of NEXT quantizer, d-major
    float  wout[DD * CD];         // 16384  out_proj (pre-loop: reused for win[0] c-major)
    float4 csq4[CS / 4];          // 4096
    float  ob[DD];                // 2048
    float  zi[CD][TTILE];         // 2048
    float  zqs[CD][TTILE];        // 2048
    float  redb[8][TTILE];        // 2048
    int    redi[8][TTILE];        // 2048
    float  part[CD][8][TTILE];    // 16384  fused z_i partials [c][dg][t]
    float  ib_all[NQ * CD];       // 288
};  // ~227.6 KB (fits 232448 B limit)

__device__ __forceinline__ float dist8(float4 ca, float4 cb2,
                                       float e0, float e1, float e2, float e3,
                                       float e4, float e5, float e6, float e7,
                                       float eq, float cs) {
    float dot = e0 * ca.x;
    dot = fmaf(e1, ca.y, dot); dot = fmaf(e2, ca.z, dot); dot = fmaf(e3, ca.w, dot);
    dot = fmaf(e4, cb2.x, dot); dot = fmaf(e5, cb2.y, dot);
    dot = fmaf(e6, cb2.z, dot); dot = fmaf(e7, cb2.w, dot);
    return fmaf(-2.0f, dot, eq) + cs;   // matches reference ((enc_sq - 2*dot) + csq)
}

__global__ void __launch_bounds__(NTHREADS, 1)
rvq_kernel(const float* __restrict__ z,
           const float* __restrict__ ib_g,
           const float* __restrict__ ob_g,
           const float* __restrict__ cbraw,
           float* __restrict__ out) {
    extern __shared__ unsigned char smraw[];
    SMem& sm = *reinterpret_cast<SMem*>(smraw);

    const int tid = threadIdx.x;
    const int b = blockIdx.y;
    const int t0 = blockIdx.x * TTILE;

    float* out_codes = out;
    float* out_zO  = out + (size_t)BB * NQ * TT;
    float* out_zis = out_zO + (size_t)BB * DD * TT;
    float* out_zqs = out_zis + (size_t)BB * NQ * CD * TT;
    float* out_zos = out_zqs + (size_t)BB * NQ * CD * TT;

    // ---- load residual tile + q=0 tables ----
    const float* zb = z + (size_t)b * DD * TT + t0;
    {
        float4* res4 = reinterpret_cast<float4*>(&sm.res[0][0]);
        for (int f = tid; f < DD * (TTILE / 4); f += NTHREADS) {
            int d = f >> 4, j = f & 15;
            res4[f] = reinterpret_cast<const float4*>(zb + (size_t)d * TT)[j];
        }
        // win[0] c-major into the wout slot (standalone z_i for q=0)
        const float4* s1 = reinterpret_cast<const float4*>(g_win);
        float4* d1 = reinterpret_cast<float4*>(&sm.wout[0]);
        for (int i = tid; i < CD * DD / 4; i += NTHREADS) d1[i] = s1[i];
        if (tid < NQ * CD) sm.ib_all[tid] = ib_g[tid];
    }
    __syncthreads();

    const int t  = tid & (TTILE - 1);   // 0..63
    const int hi = tid >> 6;            // 0..7 (c / chunk / d-group by phase)

    // ---- standalone z_i for q=0  (thread = (c=hi, t)) ----
    {
        const float4* wr4 = reinterpret_cast<const float4*>(&sm.wout[hi * DD]);
        float a0 = 0.f, a1 = 0.f, a2 = 0.f, a3 = 0.f;
        #pragma unroll 4
        for (int i = 0; i < DD / 4; i++) {
            float4 w = wr4[i];
            int d = 4 * i;
            a0 = fmaf(w.x, sm.res[d + 0][t], a0);
            a1 = fmaf(w.y, sm.res[d + 1][t], a1);
            a2 = fmaf(w.z, sm.res[d + 2][t], a2);
            a3 = fmaf(w.w, sm.res[d + 3][t], a3);
        }
        float ziv = ((a0 + a1) + (a2 + a3)) + sm.ib_all[hi];
        sm.zi[hi][t] = ziv;
        out_zis[(((size_t)b * NQ + 0) * CD + hi) * TT + t0 + t] = ziv;
    }

    for (int q = 0; q < NQ; q++) {
        __syncthreads();   // zi ready; previous-q table reads done
        // ---- stage tables for q (+ next winT) ----
        {
            const float4* s3 = reinterpret_cast<const float4*>(g_cbn + (size_t)q * CS * CD);
            for (int i = tid; i < CS * 2; i += NTHREADS) sm.cbn4[i] = s3[i];
            const float4* s4 = reinterpret_cast<const float4*>(g_csq + (size_t)q * CS);
            for (int i = tid; i < CS / 4; i += NTHREADS) sm.csq4[i] = s4[i];
            const float4* s2 = reinterpret_cast<const float4*>(g_wout + (size_t)q * DD * CD);
            float4* d2 = reinterpret_cast<float4*>(&sm.wout[0]);
            for (int i = tid; i < DD * CD / 4; i += NTHREADS) d2[i] = s2[i];
            const float4* s5 = reinterpret_cast<const float4*>(ob_g + (size_t)q * DD);
            float4* d5 = reinterpret_cast<float4*>(&sm.ob[0]);
            for (int i = tid; i < DD / 4; i += NTHREADS) d5[i] = s5[i];
            if (q < NQ - 1) {
                const float4* s6 = reinterpret_cast<const float4*>(
                    g_winT + (size_t)(q + 1) * DD * CD);
                for (int i = tid; i < DD * 2; i += NTHREADS) sm.winTn[i] = s6[i];
            }
        }
        __syncthreads();

        // ---- NN search: redundant per-thread norm, 128 codes (chunk=hi) ----
        {
            float z0 = sm.zi[0][t], z1 = sm.zi[1][t], z2 = sm.zi[2][t], z3 = sm.zi[3][t];
            float z4 = sm.zi[4][t], z5 = sm.zi[5][t], z6 = sm.zi[6][t], z7 = sm.zi[7][t];
            float ss = z0 * z0;
            ss = fmaf(z1, z1, ss); ss = fmaf(z2, z2, ss); ss = fmaf(z3, z3, ss);
            ss = fmaf(z4, z4, ss); ss = fmaf(z5, z5, ss); ss = fmaf(z6, z6, ss);
            ss = fmaf(z7, z7, ss);
            float den = fmaxf(__fsqrt_rn(ss), 1e-12f);
            float e0 = __fdiv_rn(z0, den), e1 = __fdiv_rn(z1, den);
            float e2 = __fdiv_rn(z2, den), e3 = __fdiv_rn(z3, den);
            float e4 = __fdiv_rn(z4, den), e5 = __fdiv_rn(z5, den);
            float e6 = __fdiv_rn(z6, den), e7 = __fdiv_rn(z7, den);
            float eq = e0 * e0;
            eq = fmaf(e1, e1, eq); eq = fmaf(e2, e2, eq); eq = fmaf(e3, e3, eq);
            eq = fmaf(e4, e4, eq); eq = fmaf(e5, e5, eq); eq = fmaf(e6, e6, eq);
            eq = fmaf(e7, e7, eq);

            const int s0 = hi * (CS / 8);
            float b0 = FLT_MAX, b1 = FLT_MAX, b2 = FLT_MAX, b3 = FLT_MAX;
            int   i0 = 0, i1 = 0, i2 = 0, i3 = 0;
            #pragma unroll 2
            for (int s = s0; s < s0 + CS / 8; s += 4) {
                float4 cs4 = sm.csq4[s >> 2];
                float dA = dist8(sm.cbn4[2 * s + 0], sm.cbn4[2 * s + 1], e0,e1,e2,e3,e4,e5,e6,e7, eq, cs4.x);
                float dB = dist8(sm.cbn4[2 * s + 2], sm.cbn4[2 * s + 3], e0,e1,e2,e3,e4,e5,e6,e7, eq, cs4.y);
                float dC = dist8(sm.cbn4[2 * s + 4], sm.cbn4[2 * s + 5], e0,e1,e2,e3,e4,e5,e6,e7, eq, cs4.z);
                float dDv= dist8(sm.cbn4[2 * s + 6], sm.cbn4[2 * s + 7], e0,e1,e2,e3,e4,e5,e6,e7, eq, cs4.w);
                if (dA < b0) { b0 = dA; i0 = s; }
                if (dB < b1) { b1 = dB; i1 = s + 1; }
                if (dC < b2) { b2 = dC; i2 = s + 2; }
                if (dDv< b3) { b3 = dDv; i3 = s + 3; }
            }
            if (b1 < b0 || (b1 == b0 && i1 < i0)) { b0 = b1; i0 = i1; }
            if (b2 < b0 || (b2 == b0 && i2 < i0)) { b0 = b2; i0 = i2; }
            if (b3 < b0 || (b3 == b0 && i3 < i0)) { b0 = b3; i0 = i3; }
            sm.redb[hi][t] = b0;
            sm.redi[hi][t] = i0;
        }
        __syncthreads();

        // ---- z_q: redundant argmin merge + straight-through (c=hi, t) ----
        {
            float bb = sm.redb[0][t]; int bi = sm.redi[0][t];
            #pragma unroll
            for (int g = 1; g < 8; g++) {
                float v = sm.redb[g][t];
                if (v < bb) { bb = v; bi = sm.redi[g][t]; }   // chunks ascending
            }
            if (hi == 0)
                out_codes[((size_t)b * NQ + q) * TT + t0 + t] = (float)bi;
            float ziv = sm.zi[hi][t];
            float raw = __ldg(&cbraw[((size_t)q * CS + bi) * CD + hi]);
            float zqv = ziv + (raw - ziv);
            sm.zqs[hi][t] = zqv;
            out_zqs[(((size_t)b * NQ + q) * CD + hi) * TT + t0 + t] = zqv;
        }
        __syncthreads();

        // ---- z_o (+ fused next-q z_i accumulation, or fused zO at q=8) ----
        const float q0 = sm.zqs[0][t], q1 = sm.zqs[1][t], q2 = sm.zqs[2][t], q3 = sm.zqs[3][t];
        const float q4 = sm.zqs[4][t], q5 = sm.zqs[5][t], q6 = sm.zqs[6][t], q7 = sm.zqs[7][t];
        const float4* wo4 = reinterpret_cast<const float4*>(&sm.wout[0]);
        float* zosb = out_zos + (((size_t)b * NQ + q) * DD) * TT + t0 + t;
        const int dbase = hi * 64;

        if (q < NQ - 1) {
            float ac0 = 0.f, ac1 = 0.f, ac2 = 0.f, ac3 = 0.f;
            float ac4 = 0.f, ac5 = 0.f, ac6 = 0.f, ac7 = 0.f;
            #pragma unroll 2
            for (int i = 0; i < 64; i++) {
                int d = dbase + i;
                float4 wa = wo4[2 * d], wb = wo4[2 * d + 1];
                float dot = q0 * wa.x;
                dot = fmaf(q1, wa.y, dot); dot = fmaf(q2, wa.z, dot); dot = fmaf(q3, wa.w, dot);
                dot = fmaf(q4, wb.x, dot); dot = fmaf(q5, wb.y, dot);
                dot = fmaf(q6, wb.z, dot); dot = fmaf(q7, wb.w, dot);
                float zo = dot + sm.ob[d];
                zosb[(size_t)d * TT] = zo;
                float rnew = sm.res[d][t] - zo;
                sm.res[d][t] = rnew;
                // fused next-q in-projection (weights d-major, broadcast)
                float4 na = sm.winTn[2 * d], nb = sm.winTn[2 * d + 1];
                ac0 = fmaf(rnew, na.x, ac0); ac1 = fmaf(rnew, na.y, ac1);
                ac2 = fmaf(rnew, na.z, ac2); ac3 = fmaf(rnew, na.w, ac3);
                ac4 = fmaf(rnew, nb.x, ac4); ac5 = fmaf(rnew, nb.y, ac5);
                ac6 = fmaf(rnew, nb.z, ac6); ac7 = fmaf(rnew, nb.w, ac7);
            }
            sm.part[0][hi][t] = ac0; sm.part[1][hi][t] = ac1;
            sm.part[2][hi][t] = ac2; sm.part[3][hi][t] = ac3;
            sm.part[4][hi][t] = ac4; sm.part[5][hi][t] = ac5;
            sm.part[6][hi][t] = ac6; sm.part[7][hi][t] = ac7;
            __syncthreads();
            // ---- reduce partials -> zi for q+1  (c=hi, t) ----
            {
                float s = sm.part[hi][0][t];
                #pragma unroll
                for (int dg = 1; dg < 8; dg++) s += sm.part[hi][dg][t];
                float ziv = s + sm.ib_all[(q + 1) * CD + hi];
                sm.zi[hi][t] = ziv;
                out_zis[(((size_t)b * NQ + (q + 1)) * CD + hi) * TT + t0 + t] = ziv;
            }
        } else {
            // final quantizer: fuse zO = z - res_final; no res writeback needed
            const float* zsrc = zb + t;
            float* zOb = out_zO + (size_t)b * DD * TT + t0 + t;
            #pragma unroll 2
            for (int i = 0; i < 64; i++) {
                int d = dbase + i;
                float4 wa = wo4[2 * d], wb = wo4[2 * d + 1];
                float dot = q0 * wa.x;
                dot = fmaf(q1, wa.y, dot); dot = fmaf(q2, wa.z, dot); dot = fmaf(q3, wa.w, dot);
                dot = fmaf(q4, wb.x, dot); dot = fmaf(q5, wb.y, dot);
                dot = fmaf(q6, wb.z, dot); dot = fmaf(q7, wb.w, dot);
                float zo = dot + sm.ob[d];
                zosb[(size_t)d * TT] = zo;
                float rnew = sm.res[d][t] - zo;
                zOb[(size_t)d * TT] = zsrc[(size_t)d * TT] - rnew;
            }
        }
    }
}

extern "C" void kernel_launch(void* const* d_in, const int* in_sizes, int n_in,
                              void* d_out, int out_size) {
    const float* z    = (const float*)d_in[0];
    const float* in_v = (const float*)d_in[1];
    const float* in_g = (const float*)d_in[2];
    const float* in_b = (const float*)d_in[3];
    const float* out_v= (const float*)d_in[4];
    const float* out_g= (const float*)d_in[5];
    const float* out_b= (const float*)d_in[6];
    const float* cb   = (const float*)d_in[7];
    float* out = (float*)d_out;

    rvq_precompute<<<NQ, 256>>>(in_v, in_g, out_v, out_g, cb);

    cudaFuncSetAttribute(rvq_kernel, cudaFuncAttributeMaxDynamicSharedMemorySize,
                         (int)sizeof(SMem));
    dim3 grid(TT / TTILE, BB);
    rvq_kernel<<<grid, NTHREADS, sizeof(SMem)>>>(z, in_b, out_b, cb, out);
}

// round 11
// speedup vs baseline: 1.2983x; 1.1284x over previous
#include <cuda_runtime.h>
#include <math.h>
#include <float.h>
#include <stdint.h>

#define BB 16
#define DD 512
#define TT 2048
#define NQ 9
#define CS 1024
#define CD 8
#define TTILE 64
#define NTHREADS 512

// ---------------- precomputed (normalized) parameter scratch ----------------
__device__ float g_win[NQ * CD * DD];    // weight-normed in_proj, c-major (q=0 standalone)
__device__ float g_winT[NQ * DD * CD];   // weight-normed in_proj, d-major (fused path)
__device__ float g_wout[NQ * DD * CD];   // weight-normed out_proj (q, d, c)
__device__ float g_cbn[NQ * CS * CD];    // l2-normalized codebook
__device__ float g_csq[NQ * CS];         // sum(c_norm^2) per code

__global__ void rvq_precompute(const float* __restrict__ iv, const float* __restrict__ ig,
                               const float* __restrict__ ov, const float* __restrict__ og,
                               const float* __restrict__ cb) {
    int q = blockIdx.x;
    int tid = threadIdx.x;           // 256 threads
    int wid = tid >> 5, lane = tid & 31;

    if (wid < CD) {
        int c = wid;
        const float* v = iv + ((size_t)q * CD + c) * DD;
        float ss = 0.f;
        for (int d = lane; d < DD; d += 32) { float x = v[d]; ss = fmaf(x, x, ss); }
        #pragma unroll
        for (int o = 16; o > 0; o >>= 1) ss += __shfl_xor_sync(0xffffffffu, ss, o);
        float nrm = __fsqrt_rn(ss);
        float g = ig[q * CD + c];
        for (int d = lane; d < DD; d += 32) {
            float w = __fdiv_rn(g * v[d], nrm);
            g_win[((size_t)q * CD + c) * DD + d] = w;
            g_winT[((size_t)q * DD + d) * CD + c] = w;
        }
    }
    for (int r = tid; r < DD; r += 256) {
        const float* v = ov + ((size_t)q * DD + r) * CD;
        float ss = 0.f;
        #pragma unroll
        for (int c = 0; c < CD; c++) { float x = v[c]; ss = fmaf(x, x, ss); }
        float nrm = __fsqrt_rn(ss);
        float g = og[q * DD + r];
        #pragma unroll
        for (int c = 0; c < CD; c++)
            g_wout[((size_t)q * DD + r) * CD + c] = __fdiv_rn(g * v[c], nrm);
    }
    for (int s = tid; s < CS; s += 256) {
        const float* v = cb + ((size_t)q * CS + s) * CD;
        float ss = 0.f;
        #pragma unroll
        for (int c = 0; c < CD; c++) { float x = v[c]; ss = fmaf(x, x, ss); }
        float den = fmaxf(__fsqrt_rn(ss), 1e-12f);
        float cs2 = 0.f;
        #pragma unroll
        for (int c = 0; c < CD; c++) {
            float cn = __fdiv_rn(v[c], den);
            g_cbn[((size_t)q * CS + s) * CD + c] = cn;
            cs2 = fmaf(cn, cn, cs2);
        }
        g_csq[q * CS + s] = cs2;
    }
}

// ---------------- async copy helpers ----------------
__device__ __forceinline__ void cp16(void* dst, const void* src) {
    uint32_t d = (uint32_t)__cvta_generic_to_shared(dst);
    asm volatile("cp.async.cg.shared.global [%0], [%1], 16;" :: "r"(d), "l"(src));
}
__device__ __forceinline__ void cp_commit() {
    asm volatile("cp.async.commit_group;" ::: "memory");
}
__device__ __forceinline__ void cp_wait0() {
    asm volatile("cp.async.wait_group 0;" ::: "memory");
}

// ---------------- main fused RVQ kernel ----------------
struct SMem {
    float4 cbn4[CS * 2];          // 32768  normalized codebook (async double-use buffer)
    float  res[DD][TTILE];        // 131072 residual tile
    float4 winTn[DD * 2];         // 16384  next-q in_proj, d-major
    float  wout[DD * CD];         // 16384  out_proj (pre-loop: win[0] c-major)
    float4 csq4[CS / 4];          // 4096
    float  ob[DD];                // 2048
    float  zi[CD][TTILE];         // 2048
    float  zqs[CD][TTILE];        // 2048
    union {                       // 16384 (disjoint windows: NN->z_q vs z_o->reduce)
        struct {
            float redb[16][TTILE];
            int   redi[16][TTILE];
        } nn;
        float part[CD][8][TTILE];
    } u;
    float ib_all[NQ * CD];        // 288
};  // 223520 B

__device__ __forceinline__ float dist8(float4 ca, float4 cb2,
                                       float e0, float e1, float e2, float e3,
                                       float e4, float e5, float e6, float e7,
                                       float eq, float cs) {
    float dot = e0 * ca.x;
    dot = fmaf(e1, ca.y, dot); dot = fmaf(e2, ca.z, dot); dot = fmaf(e3, ca.w, dot);
    dot = fmaf(e4, cb2.x, dot); dot = fmaf(e5, cb2.y, dot);
    dot = fmaf(e6, cb2.z, dot); dot = fmaf(e7, cb2.w, dot);
    return fmaf(-2.0f, dot, eq) + cs;   // matches reference ((enc_sq - 2*dot) + csq)
}

__global__ void __launch_bounds__(NTHREADS, 1)
rvq_kernel(const float* __restrict__ z,
           const float* __restrict__ ib_g,
           const float* __restrict__ ob_g,
           const float* __restrict__ cbraw,
           float* __restrict__ out) {
    extern __shared__ unsigned char smraw[];
    SMem& sm = *reinterpret_cast<SMem*>(smraw);

    const int tid = threadIdx.x;
    const int b = blockIdx.y;
    const int t0 = blockIdx.x * TTILE;

    float* out_codes = out;
    float* out_zO  = out + (size_t)BB * NQ * TT;
    float* out_zis = out_zO + (size_t)BB * DD * TT;
    float* out_zqs = out_zis + (size_t)BB * NQ * CD * TT;
    float* out_zos = out_zqs + (size_t)BB * NQ * CD * TT;

    // ---- load residual tile + q=0 in_proj (c-major, into wout slot) ----
    const float* zb = z + (size_t)b * DD * TT + t0;
    {
        float4* res4 = reinterpret_cast<float4*>(&sm.res[0][0]);
        for (int f = tid; f < DD * (TTILE / 4); f += NTHREADS) {
            int d = f >> 4, j = f & 15;
            res4[f] = reinterpret_cast<const float4*>(zb + (size_t)d * TT)[j];
        }
        const float4* s1 = reinterpret_cast<const float4*>(g_win);
        float4* d1 = reinterpret_cast<float4*>(&sm.wout[0]);
        for (int i = tid; i < CD * DD / 4; i += NTHREADS) d1[i] = s1[i];
        if (tid < NQ * CD) sm.ib_all[tid] = ib_g[tid];
    }
    __syncthreads();

    const int t  = tid & (TTILE - 1);   // 0..63
    const int hi = tid >> 6;            // 0..7 (c / d-group)
    const int ch = tid >> 5;            // 0..15 NN chunk of 64 codes
    const int tp = tid & 31;            // NN t-pair: t = 2tp, 2tp+1

    // ---- standalone z_i for q=0  (thread = (c=hi, t)) ----
    {
        const float4* wr4 = reinterpret_cast<const float4*>(&sm.wout[hi * DD]);
        float a0 = 0.f, a1 = 0.f, a2 = 0.f, a3 = 0.f;
        #pragma unroll 4
        for (int i = 0; i < DD / 4; i++) {
            float4 w = wr4[i];
            int d = 4 * i;
            a0 = fmaf(w.x, sm.res[d + 0][t], a0);
            a1 = fmaf(w.y, sm.res[d + 1][t], a1);
            a2 = fmaf(w.z, sm.res[d + 2][t], a2);
            a3 = fmaf(w.w, sm.res[d + 3][t], a3);
        }
        float ziv = ((a0 + a1) + (a2 + a3)) + sm.ib_all[hi];
        sm.zi[hi][t] = ziv;
        out_zis[(((size_t)b * NQ + 0) * CD + hi) * TT + t0 + t] = ziv;
    }

    for (int q = 0; q < NQ; q++) {
        cp_wait0();        // codebook prefetch for this q landed (no-op at q=0)
        __syncthreads();   // zi ready; previous-q table reads done; prefetch visible
        // ---- stage wout(q), ob(q), winT(q+1); q=0 also cbn/csq ----
        {
            const float4* s2 = reinterpret_cast<const float4*>(g_wout + (size_t)q * DD * CD);
            float4* d2 = reinterpret_cast<float4*>(&sm.wout[0]);
            for (int i = tid; i < DD * CD / 4; i += NTHREADS) d2[i] = s2[i];
            const float4* s5 = reinterpret_cast<const float4*>(ob_g + (size_t)q * DD);
            float4* d5 = reinterpret_cast<float4*>(&sm.ob[0]);
            for (int i = tid; i < DD / 4; i += NTHREADS) d5[i] = s5[i];
            if (q < NQ - 1) {
                const float4* s6 = reinterpret_cast<const float4*>(
                    g_winT + (size_t)(q + 1) * DD * CD);
                for (int i = tid; i < DD * 2; i += NTHREADS) sm.winTn[i] = s6[i];
            }
            if (q == 0) {
                const float4* s3 = reinterpret_cast<const float4*>(g_cbn);
                for (int i = tid; i < CS * 2; i += NTHREADS) sm.cbn4[i] = s3[i];
                const float4* s4 = reinterpret_cast<const float4*>(g_csq);
                for (int i = tid; i < CS / 4; i += NTHREADS) sm.csq4[i] = s4[i];
            }
        }
        __syncthreads();

        // ---- NN search: thread = (chunk ch of 64 codes, 2 t-columns) ----
        {
            const int ta = 2 * tp, tb = 2 * tp + 1;
            // per-column norms (reference summation order), both columns
            float za0 = sm.zi[0][ta], za1 = sm.zi[1][ta], za2 = sm.zi[2][ta], za3 = sm.zi[3][ta];
            float za4 = sm.zi[4][ta], za5 = sm.zi[5][ta], za6 = sm.zi[6][ta], za7 = sm.zi[7][ta];
            float zb0 = sm.zi[0][tb], zb1 = sm.zi[1][tb], zb2 = sm.zi[2][tb], zb3 = sm.zi[3][tb];
            float zb4 = sm.zi[4][tb], zb5 = sm.zi[5][tb], zb6 = sm.zi[6][tb], zb7 = sm.zi[7][tb];
            float sa = za0 * za0;
            sa = fmaf(za1, za1, sa); sa = fmaf(za2, za2, sa); sa = fmaf(za3, za3, sa);
            sa = fmaf(za4, za4, sa); sa = fmaf(za5, za5, sa); sa = fmaf(za6, za6, sa);
            sa = fmaf(za7, za7, sa);
            float sb = zb0 * zb0;
            sb = fmaf(zb1, zb1, sb); sb = fmaf(zb2, zb2, sb); sb = fmaf(zb3, zb3, sb);
            sb = fmaf(zb4, zb4, sb); sb = fmaf(zb5, zb5, sb); sb = fmaf(zb6, zb6, sb);
            sb = fmaf(zb7, zb7, sb);
            float dena = fmaxf(__fsqrt_rn(sa), 1e-12f);
            float denb = fmaxf(__fsqrt_rn(sb), 1e-12f);
            float ea0 = __fdiv_rn(za0, dena), ea1 = __fdiv_rn(za1, dena);
            float ea2 = __fdiv_rn(za2, dena), ea3 = __fdiv_rn(za3, dena);
            float ea4 = __fdiv_rn(za4, dena), ea5 = __fdiv_rn(za5, dena);
            float ea6 = __fdiv_rn(za6, dena), ea7 = __fdiv_rn(za7, dena);
            float eb0 = __fdiv_rn(zb0, denb), eb1 = __fdiv_rn(zb1, denb);
            float eb2 = __fdiv_rn(zb2, denb), eb3 = __fdiv_rn(zb3, denb);
            float eb4 = __fdiv_rn(zb4, denb), eb5 = __fdiv_rn(zb5, denb);
            float eb6 = __fdiv_rn(zb6, denb), eb7 = __fdiv_rn(zb7, denb);
            float eqa = ea0 * ea0;
            eqa = fmaf(ea1, ea1, eqa); eqa = fmaf(ea2, ea2, eqa); eqa = fmaf(ea3, ea3, eqa);
            eqa = fmaf(ea4, ea4, eqa); eqa = fmaf(ea5, ea5, eqa); eqa = fmaf(ea6, ea6, eqa);
            eqa = fmaf(ea7, ea7, eqa);
            float eqb = eb0 * eb0;
            eqb = fmaf(eb1, eb1, eqb); eqb = fmaf(eb2, eb2, eqb); eqb = fmaf(eb3, eb3, eqb);
            eqb = fmaf(eb4, eb4, eqb); eqb = fmaf(eb5, eb5, eqb); eqb = fmaf(eb6, eb6, eqb);
            eqb = fmaf(eb7, eb7, eqb);

            const float* csqs = reinterpret_cast<const float*>(sm.csq4);
            const int s0 = ch * 64;
            float bA0 = FLT_MAX, bA1 = FLT_MAX, bB0 = FLT_MAX, bB1 = FLT_MAX;
            int   iA0 = 0, iA1 = 0, iB0 = 0, iB1 = 0;
            #pragma unroll 2
            for (int s = s0; s < s0 + 64; s += 2) {
                float4 cA0 = sm.cbn4[2 * s + 0], cA1 = sm.cbn4[2 * s + 1];
                float4 cB0 = sm.cbn4[2 * s + 2], cB1 = sm.cbn4[2 * s + 3];
                float csA = csqs[s], csB = csqs[s + 1];
                float dAa = dist8(cA0, cA1, ea0,ea1,ea2,ea3,ea4,ea5,ea6,ea7, eqa, csA);
                float dAb = dist8(cA0, cA1, eb0,eb1,eb2,eb3,eb4,eb5,eb6,eb7, eqb, csA);
                float dBa = dist8(cB0, cB1, ea0,ea1,ea2,ea3,ea4,ea5,ea6,ea7, eqa, csB);
                float dBb = dist8(cB0, cB1, eb0,eb1,eb2,eb3,eb4,eb5,eb6,eb7, eqb, csB);
                if (dAa < bA0) { bA0 = dAa; iA0 = s; }
                if (dAb < bA1) { bA1 = dAb; iA1 = s; }
                if (dBa < bB0) { bB0 = dBa; iB0 = s + 1; }
                if (dBb < bB1) { bB1 = dBb; iB1 = s + 1; }
            }
            // merge even/odd chains, exact first-index tie-break
            if (bB0 < bA0 || (bB0 == bA0 && iB0 < iA0)) { bA0 = bB0; iA0 = iB0; }
            if (bB1 < bA1 || (bB1 == bA1 && iB1 < iA1)) { bA1 = bB1; iA1 = iB1; }
            sm.u.nn.redb[ch][ta] = bA0;  sm.u.nn.redi[ch][ta] = iA0;
            sm.u.nn.redb[ch][tb] = bA1;  sm.u.nn.redi[ch][tb] = iA1;
        }
        __syncthreads();

        // ---- prefetch next-q codebook (flies during z_q + z_o) ----
        if (q < NQ - 1) {
            const float4* srcC = reinterpret_cast<const float4*>(
                g_cbn + (size_t)(q + 1) * CS * CD);
            for (int i = tid; i < CS * 2; i += NTHREADS) cp16(&sm.cbn4[i], &srcC[i]);
            const float4* srcQ = reinterpret_cast<const float4*>(
                g_csq + (size_t)(q + 1) * CS);
            for (int i = tid; i < CS / 4; i += NTHREADS) cp16(&sm.csq4[i], &srcQ[i]);
            cp_commit();
        }

        // ---- z_q: redundant argmin merge (16 chunks) + straight-through (c=hi, t) ----
        {
            float bb = sm.u.nn.redb[0][t]; int bi = sm.u.nn.redi[0][t];
            #pragma unroll
            for (int g = 1; g < 16; g++) {
                float v = sm.u.nn.redb[g][t];
                if (v < bb) { bb = v; bi = sm.u.nn.redi[g][t]; }   // chunks ascending
            }
            if (hi == 0)
                out_codes[((size_t)b * NQ + q) * TT + t0 + t] = (float)bi;
            float ziv = sm.zi[hi][t];
            float raw = __ldg(&cbraw[((size_t)q * CS + bi) * CD + hi]);
            float zqv = ziv + (raw - ziv);
            sm.zqs[hi][t] = zqv;
            out_zqs[(((size_t)b * NQ + q) * CD + hi) * TT + t0 + t] = zqv;
        }
        __syncthreads();

        // ---- z_o (+ fused next-q z_i accumulation, or fused zO at q=8) ----
        const float q0 = sm.zqs[0][t], q1 = sm.zqs[1][t], q2 = sm.zqs[2][t], q3 = sm.zqs[3][t];
        const float q4 = sm.zqs[4][t], q5 = sm.zqs[5][t], q6 = sm.zqs[6][t], q7 = sm.zqs[7][t];
        const float4* wo4 = reinterpret_cast<const float4*>(&sm.wout[0]);
        float* zosb = out_zos + (((size_t)b * NQ + q) * DD) * TT + t0 + t;
        const int dbase = hi * 64;

        if (q < NQ - 1) {
            float ac0 = 0.f, ac1 = 0.f, ac2 = 0.f, ac3 = 0.f;
            float ac4 = 0.f, ac5 = 0.f, ac6 = 0.f, ac7 = 0.f;
            #pragma unroll 2
            for (int i = 0; i < 64; i++) {
                int d = dbase + i;
                float4 wa = wo4[2 * d], wb = wo4[2 * d + 1];
                float dot = q0 * wa.x;
                dot = fmaf(q1, wa.y, dot); dot = fmaf(q2, wa.z, dot); dot = fmaf(q3, wa.w, dot);
                dot = fmaf(q4, wb.x, dot); dot = fmaf(q5, wb.y, dot);
                dot = fmaf(q6, wb.z, dot); dot = fmaf(q7, wb.w, dot);
                float zo = dot + sm.ob[d];
                zosb[(size_t)d * TT] = zo;
                float rnew = sm.res[d][t] - zo;
                sm.res[d][t] = rnew;
                float4 na = sm.winTn[2 * d], nb = sm.winTn[2 * d + 1];
                ac0 = fmaf(rnew, na.x, ac0); ac1 = fmaf(rnew, na.y, ac1);
                ac2 = fmaf(rnew, na.z, ac2); ac3 = fmaf(rnew, na.w, ac3);
                ac4 = fmaf(rnew, nb.x, ac4); ac5 = fmaf(rnew, nb.y, ac5);
                ac6 = fmaf(rnew, nb.z, ac6); ac7 = fmaf(rnew, nb.w, ac7);
            }
            sm.u.part[0][hi][t] = ac0; sm.u.part[1][hi][t] = ac1;
            sm.u.part[2][hi][t] = ac2; sm.u.part[3][hi][t] = ac3;
            sm.u.part[4][hi][t] = ac4; sm.u.part[5][hi][t] = ac5;
            sm.u.part[6][hi][t] = ac6; sm.u.part[7][hi][t] = ac7;
            __syncthreads();
            // ---- reduce partials -> zi for q+1  (c=hi, t) ----
            {
                float s = sm.u.part[hi][0][t];
                #pragma unroll
                for (int dg = 1; dg < 8; dg++) s += sm.u.part[hi][dg][t];
                float ziv = s + sm.ib_all[(q + 1) * CD + hi];
                sm.zi[hi][t] = ziv;
                out_zis[(((size_t)b * NQ + (q + 1)) * CD + hi) * TT + t0 + t] = ziv;
            }
        } else {
            // final quantizer: fuse zO = z - res_final
            const float* zsrc = zb + t;
            float* zOb = out_zO + (size_t)b * DD * TT + t0 + t;
            #pragma unroll 2
            for (int i = 0; i < 64; i++) {
                int d = dbase + i;
                float4 wa = wo4[2 * d], wb = wo4[2 * d + 1];
                float dot = q0 * wa.x;
                dot = fmaf(q1, wa.y, dot); dot = fmaf(q2, wa.z, dot); dot = fmaf(q3, wa.w, dot);
                dot = fmaf(q4, wb.x, dot); dot = fmaf(q5, wb.y, dot);
                dot = fmaf(q6, wb.z, dot); dot = fmaf(q7, wb.w, dot);
                float zo = dot + sm.ob[d];
                zosb[(size_t)d * TT] = zo;
                float rnew = sm.res[d][t] - zo;
                zOb[(size_t)d * TT] = zsrc[(size_t)d * TT] - rnew;
            }
        }
    }
}

extern "C" void kernel_launch(void* const* d_in, const int* in_sizes, int n_in,
                              void* d_out, int out_size) {
    const float* z    = (const float*)d_in[0];
    const float* in_v = (const float*)d_in[1];
    const float* in_g = (const float*)d_in[2];
    const float* in_b = (const float*)d_in[3];
    const float* out_v= (const float*)d_in[4];
    const float* out_g= (const float*)d_in[5];
    const float* out_b= (const float*)d_in[6];
    const float* cb   = (const float*)d_in[7];
    float* out = (float*)d_out;

    rvq_precompute<<<NQ, 256>>>(in_v, in_g, out_v, out_g, cb);

    cudaFuncSetAttribute(rvq_kernel, cudaFuncAttributeMaxDynamicSharedMemorySize,
                         (int)sizeof(SMem));
    dim3 grid(TT / TTILE, BB);
    rvq_kernel<<<grid, NTHREADS, sizeof(SMem)>>>(z, in_b, out_b, cb, out);
}

// round 12
// speedup vs baseline: 1.3857x; 1.0673x over previous
#include <cuda_runtime.h>
#include <math.h>
#include <float.h>
#include <stdint.h>

#define BB 16
#define DD 512
#define TT 2048
#define NQ 9
#define CS 1024
#define CD 8
#define TTILE 64
#define NTHREADS 512

typedef unsigned long long ull;

__device__ __forceinline__ ull pk2(float lo, float hi) {
    ull r; asm("mov.b64 %0,{%1,%2};" : "=l"(r) : "f"(lo), "f"(hi)); return r;
}
__device__ __forceinline__ void upk2(float& lo, float& hi, ull v) {
    asm("mov.b64 {%0,%1},%2;" : "=f"(lo), "=f"(hi) : "l"(v));
}
__device__ __forceinline__ ull fma2(ull a, ull b, ull c) {
    ull d; asm("fma.rn.f32x2 %0,%1,%2,%3;" : "=l"(d) : "l"(a), "l"(b), "l"(c)); return d;
}
__device__ __forceinline__ ull mul2(ull a, ull b) {
    ull d; asm("mul.rn.f32x2 %0,%1,%2;" : "=l"(d) : "l"(a), "l"(b)); return d;
}

// ---------------- precomputed (normalized) parameter scratch ----------------
__device__ float g_win[NQ * CD * DD];    // weight-normed in_proj, c-major (q=0 standalone)
__device__ float g_winT[NQ * DD * CD];   // weight-normed in_proj, d-major (fused path)
__device__ float g_woutT[NQ * CD * DD];  // weight-normed out_proj TRANSPOSED (q, c, d)
__device__ float g_cbn[NQ * CS * CD];    // l2-normalized codebook
__device__ float g_csq[NQ * CS];         // sum(c_norm^2) per code

__global__ void rvq_precompute(const float* __restrict__ iv, const float* __restrict__ ig,
                               const float* __restrict__ ov, const float* __restrict__ og,
                               const float* __restrict__ cb) {
    int q = blockIdx.x;
    int tid = threadIdx.x;           // 256 threads
    int wid = tid >> 5, lane = tid & 31;

    if (wid < CD) {
        int c = wid;
        const float* v = iv + ((size_t)q * CD + c) * DD;
        float ss = 0.f;
        for (int d = lane; d < DD; d += 32) { float x = v[d]; ss = fmaf(x, x, ss); }
        #pragma unroll
        for (int o = 16; o > 0; o >>= 1) ss += __shfl_xor_sync(0xffffffffu, ss, o);
        float nrm = __fsqrt_rn(ss);
        float g = ig[q * CD + c];
        for (int d = lane; d < DD; d += 32) {
            float w = __fdiv_rn(g * v[d], nrm);
            g_win[((size_t)q * CD + c) * DD + d] = w;
            g_winT[((size_t)q * DD + d) * CD + c] = w;
        }
    }
    for (int r = tid; r < DD; r += 256) {
        const float* v = ov + ((size_t)q * DD + r) * CD;
        float ss = 0.f;
        #pragma unroll
        for (int c = 0; c < CD; c++) { float x = v[c]; ss = fmaf(x, x, ss); }
        float nrm = __fsqrt_rn(ss);
        float g = og[q * DD + r];
        #pragma unroll
        for (int c = 0; c < CD; c++)
            g_woutT[((size_t)q * CD + c) * DD + r] = __fdiv_rn(g * v[c], nrm);
    }
    for (int s = tid; s < CS; s += 256) {
        const float* v = cb + ((size_t)q * CS + s) * CD;
        float ss = 0.f;
        #pragma unroll
        for (int c = 0; c < CD; c++) { float x = v[c]; ss = fmaf(x, x, ss); }
        float den = fmaxf(__fsqrt_rn(ss), 1e-12f);
        float cs2 = 0.f;
        #pragma unroll
        for (int c = 0; c < CD; c++) {
            float cn = __fdiv_rn(v[c], den);
            g_cbn[((size_t)q * CS + s) * CD + c] = cn;
            cs2 = fmaf(cn, cn, cs2);
        }
        g_csq[q * CS + s] = cs2;
    }
}

// ---------------- async copy helpers ----------------
__device__ __forceinline__ void cp16(void* dst, const void* src) {
    uint32_t d = (uint32_t)__cvta_generic_to_shared(dst);
    asm volatile("cp.async.cg.shared.global [%0], [%1], 16;" :: "r"(d), "l"(src));
}
__device__ __forceinline__ void cp_commit() {
    asm volatile("cp.async.commit_group;" ::: "memory");
}
__device__ __forceinline__ void cp_wait0() {
    asm volatile("cp.async.wait_group 0;" ::: "memory");
}

// ---------------- main fused RVQ kernel ----------------
struct SMem {
    float4 cbn4[CS * 2];          // 32768  normalized codebook (async-prefetched)
    float  res[DD][TTILE];        // 131072 residual tile
    float4 winTn[DD * 2];         // 16384  next-q in_proj, d-major
    float  woutT[CD * DD];        // 16384  out_proj c-major (pre-loop: win[0] c-major)
    float4 csq4[CS / 4];          // 4096
    float  ob[DD];                // 2048
    float  zi[CD][TTILE];         // 2048
    float  zqs[CD][TTILE];        // 2048
    union {                       // 16384 (disjoint windows: NN->z_q vs z_o->reduce)
        struct {
            float redb[16][TTILE];
            int   redi[16][TTILE];
        } nn;
        float part[CD][8][TTILE];
    } u;
    float ib_all[NQ * CD];        // 288
};  // 223520 B

__device__ __forceinline__ float dist8(float4 ca, float4 cb2,
                                       float e0, float e1, float e2, float e3,
                                       float e4, float e5, float e6, float e7,
                                       float eq, float cs) {
    float dot = e0 * ca.x;
    dot = fmaf(e1, ca.y, dot); dot = fmaf(e2, ca.z, dot); dot = fmaf(e3, ca.w, dot);
    dot = fmaf(e4, cb2.x, dot); dot = fmaf(e5, cb2.y, dot);
    dot = fmaf(e6, cb2.z, dot); dot = fmaf(e7, cb2.w, dot);
    return fmaf(-2.0f, dot, eq) + cs;   // matches reference ((enc_sq - 2*dot) + csq)
}

// packed out-projection for 4 consecutive d (bit-identical per-lane chain):
// lane k: dot = q0*w[d+k][0]; fma over c=1..7 in order.
__device__ __forceinline__ void outproj4(const ulonglong2* wt, int wi,
                                         const ull* qq, ull& a01, ull& a23) {
    ulonglong2 wc = wt[wi];
    a01 = mul2(qq[0], wc.x);  a23 = mul2(qq[0], wc.y);
    #pragma unroll
    for (int c = 1; c < CD; c++) {
        wc = wt[c * (DD / 4) + wi];
        a01 = fma2(qq[c], wc.x, a01);
        a23 = fma2(qq[c], wc.y, a23);
    }
}

__global__ void __launch_bounds__(NTHREADS, 1)
rvq_kernel(const float* __restrict__ z,
           const float* __restrict__ ib_g,
           const float* __restrict__ ob_g,
           const float* __restrict__ cbraw,
           float* __restrict__ out) {
    extern __shared__ unsigned char smraw[];
    SMem& sm = *reinterpret_cast<SMem*>(smraw);

    const int tid = threadIdx.x;
    const int b = blockIdx.y;
    const int t0 = blockIdx.x * TTILE;

    float* out_codes = out;
    float* out_zO  = out + (size_t)BB * NQ * TT;
    float* out_zis = out_zO + (size_t)BB * DD * TT;
    float* out_zqs = out_zis + (size_t)BB * NQ * CD * TT;
    float* out_zos = out_zqs + (size_t)BB * NQ * CD * TT;

    // ---- load residual tile + q=0 in_proj (c-major, into woutT slot) ----
    const float* zb = z + (size_t)b * DD * TT + t0;
    {
        float4* res4 = reinterpret_cast<float4*>(&sm.res[0][0]);
        for (int f = tid; f < DD * (TTILE / 4); f += NTHREADS) {
            int d = f >> 4, j = f & 15;
            res4[f] = reinterpret_cast<const float4*>(zb + (size_t)d * TT)[j];
        }
        const float4* s1 = reinterpret_cast<const float4*>(g_win);
        float4* d1 = reinterpret_cast<float4*>(&sm.woutT[0]);
        for (int i = tid; i < CD * DD / 4; i += NTHREADS) d1[i] = s1[i];
        if (tid < NQ * CD) sm.ib_all[tid] = ib_g[tid];
    }
    __syncthreads();

    const int t  = tid & (TTILE - 1);   // 0..63
    const int hi = tid >> 6;            // 0..7 (c / d-group)
    const int ch = tid >> 5;            // 0..15 NN chunk of 64 codes
    const int tp = tid & 31;            // NN t-pair: t = 2tp, 2tp+1

    // ---- standalone z_i for q=0  (thread = (c=hi, t)) ----
    {
        const float4* wr4 = reinterpret_cast<const float4*>(&sm.woutT[hi * DD]);
        float a0 = 0.f, a1 = 0.f, a2 = 0.f, a3 = 0.f;
        #pragma unroll 4
        for (int i = 0; i < DD / 4; i++) {
            float4 w = wr4[i];
            int d = 4 * i;
            a0 = fmaf(w.x, sm.res[d + 0][t], a0);
            a1 = fmaf(w.y, sm.res[d + 1][t], a1);
            a2 = fmaf(w.z, sm.res[d + 2][t], a2);
            a3 = fmaf(w.w, sm.res[d + 3][t], a3);
        }
        float ziv = ((a0 + a1) + (a2 + a3)) + sm.ib_all[hi];
        sm.zi[hi][t] = ziv;
        out_zis[(((size_t)b * NQ + 0) * CD + hi) * TT + t0 + t] = ziv;
    }

    for (int q = 0; q < NQ; q++) {
        cp_wait0();        // codebook prefetch for this q landed (no-op at q=0)
        __syncthreads();   // zi ready; previous-q table reads done; prefetch visible
        // ---- stage woutT(q), ob(q), winT(q+1); q=0 also cbn/csq ----
        {
            const float4* s2 = reinterpret_cast<const float4*>(g_woutT + (size_t)q * CD * DD);
            float4* d2 = reinterpret_cast<float4*>(&sm.woutT[0]);
            for (int i = tid; i < CD * DD / 4; i += NTHREADS) d2[i] = s2[i];
            const float4* s5 = reinterpret_cast<const float4*>(ob_g + (size_t)q * DD);
            float4* d5 = reinterpret_cast<float4*>(&sm.ob[0]);
            for (int i = tid; i < DD / 4; i += NTHREADS) d5[i] = s5[i];
            if (q < NQ - 1) {
                const float4* s6 = reinterpret_cast<const float4*>(
                    g_winT + (size_t)(q + 1) * DD * CD);
                for (int i = tid; i < DD * 2; i += NTHREADS) sm.winTn[i] = s6[i];
            }
            if (q == 0) {
                const float4* s3 = reinterpret_cast<const float4*>(g_cbn);
                for (int i = tid; i < CS * 2; i += NTHREADS) sm.cbn4[i] = s3[i];
                const float4* s4 = reinterpret_cast<const float4*>(g_csq);
                for (int i = tid; i < CS / 4; i += NTHREADS) sm.csq4[i] = s4[i];
            }
        }
        __syncthreads();

        // ---- NN search: thread = (chunk ch of 64 codes, 2 t-columns) ----
        {
            const int ta = 2 * tp, tb = 2 * tp + 1;
            float za0 = sm.zi[0][ta], za1 = sm.zi[1][ta], za2 = sm.zi[2][ta], za3 = sm.zi[3][ta];
            float za4 = sm.zi[4][ta], za5 = sm.zi[5][ta], za6 = sm.zi[6][ta], za7 = sm.zi[7][ta];
            float zb0 = sm.zi[0][tb], zb1 = sm.zi[1][tb], zb2 = sm.zi[2][tb], zb3 = sm.zi[3][tb];
            float zb4 = sm.zi[4][tb], zb5 = sm.zi[5][tb], zb6 = sm.zi[6][tb], zb7 = sm.zi[7][tb];
            float sa = za0 * za0;
            sa = fmaf(za1, za1, sa); sa = fmaf(za2, za2, sa); sa = fmaf(za3, za3, sa);
            sa = fmaf(za4, za4, sa); sa = fmaf(za5, za5, sa); sa = fmaf(za6, za6, sa);
            sa = fmaf(za7, za7, sa);
            float sb = zb0 * zb0;
            sb = fmaf(zb1, zb1, sb); sb = fmaf(zb2, zb2, sb); sb = fmaf(zb3, zb3, sb);
            sb = fmaf(zb4, zb4, sb); sb = fmaf(zb5, zb5, sb); sb = fmaf(zb6, zb6, sb);
            sb = fmaf(zb7, zb7, sb);
            float dena = fmaxf(__fsqrt_rn(sa), 1e-12f);
            float denb = fmaxf(__fsqrt_rn(sb), 1e-12f);
            float ea0 = __fdiv_rn(za0, dena), ea1 = __fdiv_rn(za1, dena);
            float ea2 = __fdiv_rn(za2, dena), ea3 = __fdiv_rn(za3, dena);
            float ea4 = __fdiv_rn(za4, dena), ea5 = __fdiv_rn(za5, dena);
            float ea6 = __fdiv_rn(za6, dena), ea7 = __fdiv_rn(za7, dena);
            float eb0 = __fdiv_rn(zb0, denb), eb1 = __fdiv_rn(zb1, denb);
            float eb2 = __fdiv_rn(zb2, denb), eb3 = __fdiv_rn(zb3, denb);
            float eb4 = __fdiv_rn(zb4, denb), eb5 = __fdiv_rn(zb5, denb);
            float eb6 = __fdiv_rn(zb6, denb), eb7 = __fdiv_rn(zb7, denb);
            float eqa = ea0 * ea0;
            eqa = fmaf(ea1, ea1, eqa); eqa = fmaf(ea2, ea2, eqa); eqa = fmaf(ea3, ea3, eqa);
            eqa = fmaf(ea4, ea4, eqa); eqa = fmaf(ea5, ea5, eqa); eqa = fmaf(ea6, ea6, eqa);
            eqa = fmaf(ea7, ea7, eqa);
            float eqb = eb0 * eb0;
            eqb = fmaf(eb1, eb1, eqb); eqb = fmaf(eb2, eb2, eqb); eqb = fmaf(eb3, eb3, eqb);
            eqb = fmaf(eb4, eb4, eqb); eqb = fmaf(eb5, eb5, eqb); eqb = fmaf(eb6, eb6, eqb);
            eqb = fmaf(eb7, eb7, eqb);

            const float* csqs = reinterpret_cast<const float*>(sm.csq4);
            const int s0 = ch * 64;
            float bA0 = FLT_MAX, bA1 = FLT_MAX, bB0 = FLT_MAX, bB1 = FLT_MAX;
            int   iA0 = 0, iA1 = 0, iB0 = 0, iB1 = 0;
            #pragma unroll 2
            for (int s = s0; s < s0 + 64; s += 2) {
                float4 cA0 = sm.cbn4[2 * s + 0], cA1 = sm.cbn4[2 * s + 1];
                float4 cB0 = sm.cbn4[2 * s + 2], cB1 = sm.cbn4[2 * s + 3];
                float2 csv = *reinterpret_cast<const float2*>(csqs + s);
                float dAa = dist8(cA0, cA1, ea0,ea1,ea2,ea3,ea4,ea5,ea6,ea7, eqa, csv.x);
                float dAb = dist8(cA0, cA1, eb0,eb1,eb2,eb3,eb4,eb5,eb6,eb7, eqb, csv.x);
                float dBa = dist8(cB0, cB1, ea0,ea1,ea2,ea3,ea4,ea5,ea6,ea7, eqa, csv.y);
                float dBb = dist8(cB0, cB1, eb0,eb1,eb2,eb3,eb4,eb5,eb6,eb7, eqb, csv.y);
                if (dAa < bA0) { bA0 = dAa; iA0 = s; }
                if (dAb < bA1) { bA1 = dAb; iA1 = s; }
                if (dBa < bB0) { bB0 = dBa; iB0 = s + 1; }
                if (dBb < bB1) { bB1 = dBb; iB1 = s + 1; }
            }
            if (bB0 < bA0 || (bB0 == bA0 && iB0 < iA0)) { bA0 = bB0; iA0 = iB0; }
            if (bB1 < bA1 || (bB1 == bA1 && iB1 < iA1)) { bA1 = bB1; iA1 = iB1; }
            sm.u.nn.redb[ch][ta] = bA0;  sm.u.nn.redi[ch][ta] = iA0;
            sm.u.nn.redb[ch][tb] = bA1;  sm.u.nn.redi[ch][tb] = iA1;
        }
        __syncthreads();

        // ---- prefetch next-q codebook (flies during z_q + z_o) ----
        if (q < NQ - 1) {
            const float4* srcC = reinterpret_cast<const float4*>(
                g_cbn + (size_t)(q + 1) * CS * CD);
            for (int i = tid; i < CS * 2; i += NTHREADS) cp16(&sm.cbn4[i], &srcC[i]);
            const float4* srcQ = reinterpret_cast<const float4*>(
                g_csq + (size_t)(q + 1) * CS);
            for (int i = tid; i < CS / 4; i += NTHREADS) cp16(&sm.csq4[i], &srcQ[i]);
            cp_commit();
        }

        // ---- z_q: redundant argmin merge (16 chunks) + straight-through (c=hi, t) ----
        {
            float bb = sm.u.nn.redb[0][t]; int bi = sm.u.nn.redi[0][t];
            #pragma unroll
            for (int g = 1; g < 16; g++) {
                float v = sm.u.nn.redb[g][t];
                if (v < bb) { bb = v; bi = sm.u.nn.redi[g][t]; }   // chunks ascending
            }
            if (hi == 0)
                out_codes[((size_t)b * NQ + q) * TT + t0 + t] = (float)bi;
            float ziv = sm.zi[hi][t];
            float raw = __ldg(&cbraw[((size_t)q * CS + bi) * CD + hi]);
            float zqv = ziv + (raw - ziv);
            sm.zqs[hi][t] = zqv;
            out_zqs[(((size_t)b * NQ + q) * CD + hi) * TT + t0 + t] = zqv;
        }
        __syncthreads();

        // ---- z_o (packed) + fused next-q z_i accumulation, or fused zO at q=8 ----
        ull qq[CD];
        {
            #pragma unroll
            for (int c = 0; c < CD; c++) {
                float v = sm.zqs[c][t];
                qq[c] = pk2(v, v);
            }
        }
        const ulonglong2* wt = reinterpret_cast<const ulonglong2*>(&sm.woutT[0]);
        const ulonglong2* wn = reinterpret_cast<const ulonglong2*>(&sm.winTn[0]);
        const float4* ob4 = reinterpret_cast<const float4*>(&sm.ob[0]);
        float* zosb = out_zos + (((size_t)b * NQ + q) * DD) * TT + t0 + t;
        const int dbase = hi * 64;

        if (q < NQ - 1) {
            ull ac01 = 0ull, ac23 = 0ull, ac45 = 0ull, ac67 = 0ull;
            #pragma unroll 2
            for (int i = 0; i < 16; i++) {
                const int d = dbase + 4 * i;
                const int wi = d >> 2;
                ull a01, a23;
                outproj4(wt, wi, qq, a01, a23);
                float4 obv = ob4[wi];
                float z0v, z1v, z2v, z3v;
                upk2(z0v, z1v, a01); upk2(z2v, z3v, a23);
                float zo0 = z0v + obv.x, zo1 = z1v + obv.y;
                float zo2 = z2v + obv.z, zo3 = z3v + obv.w;
                zosb[(size_t)(d + 0) * TT] = zo0;
                zosb[(size_t)(d + 1) * TT] = zo1;
                zosb[(size_t)(d + 2) * TT] = zo2;
                zosb[(size_t)(d + 3) * TT] = zo3;
                float r0 = sm.res[d + 0][t] - zo0; sm.res[d + 0][t] = r0;
                float r1 = sm.res[d + 1][t] - zo1; sm.res[d + 1][t] = r1;
                float r2v= sm.res[d + 2][t] - zo2; sm.res[d + 2][t] = r2v;
                float r3 = sm.res[d + 3][t] - zo3; sm.res[d + 3][t] = r3;
                // fused next-q in-projection, packed over c-pairs (d-serial per lane)
                {
                    ull rr = pk2(r0, r0);
                    ulonglong2 na = wn[2 * (d + 0)], nb = wn[2 * (d + 0) + 1];
                    ac01 = fma2(rr, na.x, ac01); ac23 = fma2(rr, na.y, ac23);
                    ac45 = fma2(rr, nb.x, ac45); ac67 = fma2(rr, nb.y, ac67);
                }
                {
                    ull rr = pk2(r1, r1);
                    ulonglong2 na = wn[2 * (d + 1)], nb = wn[2 * (d + 1) + 1];
                    ac01 = fma2(rr, na.x, ac01); ac23 = fma2(rr, na.y, ac23);
                    ac45 = fma2(rr, nb.x, ac45); ac67 = fma2(rr, nb.y, ac67);
                }
                {
                    ull rr = pk2(r2v, r2v);
                    ulonglong2 na = wn[2 * (d + 2)], nb = wn[2 * (d + 2) + 1];
                    ac01 = fma2(rr, na.x, ac01); ac23 = fma2(rr, na.y, ac23);
                    ac45 = fma2(rr, nb.x, ac45); ac67 = fma2(rr, nb.y, ac67);
                }
                {
                    ull rr = pk2(r3, r3);
                    ulonglong2 na = wn[2 * (d + 3)], nb = wn[2 * (d + 3) + 1];
                    ac01 = fma2(rr, na.x, ac01); ac23 = fma2(rr, na.y, ac23);
                    ac45 = fma2(rr, nb.x, ac45); ac67 = fma2(rr, nb.y, ac67);
                }
            }
            {
                float p0, p1, p2, p3, p4, p5, p6, p7;
                upk2(p0, p1, ac01); upk2(p2, p3, ac23);
                upk2(p4, p5, ac45); upk2(p6, p7, ac67);
                sm.u.part[0][hi][t] = p0; sm.u.part[1][hi][t] = p1;
                sm.u.part[2][hi][t] = p2; sm.u.part[3][hi][t] = p3;
                sm.u.part[4][hi][t] = p4; sm.u.part[5][hi][t] = p5;
                sm.u.part[6][hi][t] = p6; sm.u.part[7][hi][t] = p7;
            }
            __syncthreads();
            // ---- reduce partials -> zi for q+1  (c=hi, t) ----
            {
                float s = sm.u.part[hi][0][t];
                #pragma unroll
                for (int dg = 1; dg < 8; dg++) s += sm.u.part[hi][dg][t];
                float ziv = s + sm.ib_all[(q + 1) * CD + hi];
                sm.zi[hi][t] = ziv;
                out_zis[(((size_t)b * NQ + (q + 1)) * CD + hi) * TT + t0 + t] = ziv;
            }
        } else {
            // final quantizer: fuse zO = z - res_final
            const float* zsrc = zb + t;
            float* zOb = out_zO + (size_t)b * DD * TT + t0 + t;
            #pragma unroll 2
            for (int i = 0; i < 16; i++) {
                const int d = dbase + 4 * i;
                const int wi = d >> 2;
                ull a01, a23;
                outproj4(wt, wi, qq, a01, a23);
                float4 obv = ob4[wi];
                float z0v, z1v, z2v, z3v;
                upk2(z0v, z1v, a01); upk2(z2v, z3v, a23);
                float zo0 = z0v + obv.x, zo1 = z1v + obv.y;
                float zo2 = z2v + obv.z, zo3 = z3v + obv.w;
                zosb[(size_t)(d + 0) * TT] = zo0;
                zosb[(size_t)(d + 1) * TT] = zo1;
                zosb[(size_t)(d + 2) * TT] = zo2;
                zosb[(size_t)(d + 3) * TT] = zo3;
                float r0 = sm.res[d + 0][t] - zo0;
                float r1 = sm.res[d + 1][t] - zo1;
                float r2v= sm.res[d + 2][t] - zo2;
                float r3 = sm.res[d + 3][t] - zo3;
                zOb[(size_t)(d + 0) * TT] = zsrc[(size_t)(d + 0) * TT] - r0;
                zOb[(size_t)(d + 1) * TT] = zsrc[(size_t)(d + 1) * TT] - r1;
                zOb[(size_t)(d + 2) * TT] = zsrc[(size_t)(d + 2) * TT] - r2v;
                zOb[(size_t)(d + 3) * TT] = zsrc[(size_t)(d + 3) * TT] - r3;
            }
        }
    }
}

extern "C" void kernel_launch(void* const* d_in, const int* in_sizes, int n_in,
                              void* d_out, int out_size) {
    const float* z    = (const float*)d_in[0];
    const float* in_v = (const float*)d_in[1];
    const float* in_g = (const float*)d_in[2];
    const float* in_b = (const float*)d_in[3];
    const float* out_v= (const float*)d_in[4];
    const float* out_g= (const float*)d_in[5];
    const float* out_b= (const float*)d_in[6];
    const float* cb   = (const float*)d_in[7];
    float* out = (float*)d_out;

    rvq_precompute<<<NQ, 256>>>(in_v, in_g, out_v, out_g, cb);

    cudaFuncSetAttribute(rvq_kernel, cudaFuncAttributeMaxDynamicSharedMemorySize,
                         (int)sizeof(SMem));
    dim3 grid(TT / TTILE, BB);
    rvq_kernel<<<grid, NTHREADS, sizeof(SMem)>>>(z, in_b, out_b, cb, out);
}